// round 16
// baseline (speedup 1.0000x reference)
#include <cuda_runtime.h>
#include <cuda_bf16.h>
#include <cstdint>

// NVAR feature expansion:
//   X: (8, 4, 4096) f32  ->  out: (8, 4, 3996, 231) f32
//   features per (b,r,t): [1, tap_0..tap_9, 220 degree-3 monomials (i<=j<=k)]
//   tap_k = X[b, r, t + 2k - 18], t = tout + 100  (always in-bounds)

#define KTAPS   10
#define NMON    220
#define NF      231                 // 1 + KTAPS + NMON
#define NT_IN   4096
#define TRANS   100
#define NT_OUT  (NT_IN - TRANS)     // 3996
#define PADL    18                  // (KTAPS-1)*SKIP
#define TILE_T  32
#define NTHREADS 256
#define TILE_F4  ((TILE_T * NF) / 4)   // 1848 float4 per full tile
#define N4_STG   (6 * 224)             // 1344 float4 drained by warps 0..6 via stcs
#define N4_TMA   (TILE_F4 - N4_STG)    // 504 float4 = 8064 B drained by TMA

// Per-group feature ranges over [0, 231): groups 0..6 get 29, group 7 gets 28.
template <int G>
__device__ __forceinline__ void do_feats(const float (&x)[KTAPS], float* __restrict__ srow) {
    constexpr int LO = G * 29;
    constexpr int HI = (G == 7) ? NF : LO + 29;

    if (LO == 0) srow[0] = 1.0f;

    #pragma unroll
    for (int t = 0; t < KTAPS; ++t)
        if (t + 1 >= LO && t + 1 < HI) srow[t + 1] = x[t];

    // monomials in lexicographic (a<=b<=c) order; product ((xa*xb)*xc) == jnp.prod order
    int m = 0;
    #pragma unroll
    for (int a = 0; a < KTAPS; ++a) {
        #pragma unroll
        for (int b = a; b < KTAPS; ++b) {
            float xab = x[a] * x[b];            // DCE'd when no store lands in [LO,HI)
            #pragma unroll
            for (int c = b; c < KTAPS; ++c) {
                int f = 1 + KTAPS + m;
                if (f >= LO && f < HI) srow[f] = xab * x[c];
                ++m;
            }
        }
    }
}

__device__ __forceinline__ uint32_t smem_u32(const void* p) {
    uint32_t a;
    asm("{ .reg .u64 t; cvta.to.shared.u64 t, %1; cvt.u32.u64 %0, t; }" : "=r"(a) : "l"(p));
    return a;
}

__global__ __launch_bounds__(NTHREADS)
void nvar_kernel(const float* __restrict__ X, float* __restrict__ out) {
    __shared__ alignas(16) float s_out[TILE_T * NF];    // 29568 B, layout == global rows

    const int tid   = threadIdx.x;
    const int tl    = tid & (TILE_T - 1);       // time-step within tile (0..31)
    const int g     = tid >> 5;                 // warp id = feature group (0..7)
    const int br    = blockIdx.y;               // b*4 + r, 0..31
    const int t0    = blockIdx.x * TILE_T;
    const int valid = min(TILE_T, NT_OUT - t0); // 32, or 28 on the last tile

    if (tl < valid) {
        const float* Xtap = X + (size_t)br * NT_IN + (TRANS - PADL) + t0 + tl;
        float x[KTAPS];
        #pragma unroll
        for (int t = 0; t < KTAPS; ++t)
            x[t] = __ldg(Xtap + 2 * t);                  // L1-hot, coalesced per warp

        float* srow = s_out + tl * NF;          // stride 231 words -> 32 distinct banks
        switch (g) {                            // warp-uniform, no divergence
            case 0: do_feats<0>(x, srow); break;
            case 1: do_feats<1>(x, srow); break;
            case 2: do_feats<2>(x, srow); break;
            case 3: do_feats<3>(x, srow); break;
            case 4: do_feats<4>(x, srow); break;
            case 5: do_feats<5>(x, srow); break;
            case 6: do_feats<6>(x, srow); break;
            default: do_feats<7>(x, srow); break;
        }
    }
    __syncthreads();

    // Hybrid drain. Tile is a flat, 16B-aligned run of valid*NF floats
    // ((br*3996 + t0)*924 % 16 == 0).
    //  - warps 0..6: fire-and-forget __stcs of the first 1344 float4 (6 iters each)
    //    -> no wait, keeps issue duty up, streaming L2 semantics (proven win).
    //  - warp 7 lane 0: TMA bulk copy of the last 8064 B with evict_first hint
    //    -> removes 27% of LDS+STG wavefronts from the LSU; the blocking
    //       wait now covers only 8 KB instead of 29.5 KB.
    const float4* s4 = reinterpret_cast<const float4*>(s_out);
    float4* g4 = reinterpret_cast<float4*>(out + ((size_t)br * NT_OUT + t0) * NF);

    if (valid == TILE_T) {
        if (tid < 224) {
            float4 v0 = s4[tid + 0 * 224];
            float4 v1 = s4[tid + 1 * 224];
            float4 v2 = s4[tid + 2 * 224];
            float4 v3 = s4[tid + 3 * 224];
            float4 v4 = s4[tid + 4 * 224];
            float4 v5 = s4[tid + 5 * 224];
            __stcs(g4 + tid + 0 * 224, v0);
            __stcs(g4 + tid + 1 * 224, v1);
            __stcs(g4 + tid + 2 * 224, v2);
            __stcs(g4 + tid + 3 * 224, v3);
            __stcs(g4 + tid + 4 * 224, v4);
            __stcs(g4 + tid + 5 * 224, v5);
        } else if (tid == 224) {
            uint32_t src    = smem_u32(s_out) + N4_STG * 16;
            float*   gdst   = reinterpret_cast<float*>(g4 + N4_STG);
            uint64_t pol;
            asm volatile("createpolicy.fractional.L2::evict_first.b64 %0, 1.0;" : "=l"(pol));
            asm volatile("fence.proxy.async.shared::cta;" ::: "memory");
            asm volatile("cp.async.bulk.global.shared::cta.bulk_group.L2::cache_hint"
                         " [%0], [%1], %2, %3;"
                         :: "l"(gdst), "r"(src), "n"(N4_TMA * 16), "l"(pol) : "memory");
            asm volatile("cp.async.bulk.commit_group;" ::: "memory");
            asm volatile("cp.async.bulk.wait_group 0;" ::: "memory");
        }
    } else {
        const int n4 = (valid * NF) >> 2;       // 1617 on the single partial tile
        #pragma unroll 4
        for (int i = tid; i < n4; i += NTHREADS)
            __stcs(g4 + i, s4[i]);
    }
}

extern "C" void kernel_launch(void* const* d_in, const int* in_sizes, int n_in,
                              void* d_out, int out_size) {
    const float* X   = (const float*)d_in[0];
    float*       out = (float*)d_out;

    const int br_total = in_sizes[0] / NT_IN;                 // 32
    dim3 grid((NT_OUT + TILE_T - 1) / TILE_T, br_total);      // 125 x 32 = 4000 blocks
    nvar_kernel<<<grid, NTHREADS>>>(X, out);
}